// round 2
// baseline (speedup 1.0000x reference)
#include <cuda_runtime.h>
#include <math.h>

#define NN 20000
#define EE 320000
#define HH 128
#define NTILES_N ((NN + 63) / 64)   /* 313 */
#define NTILES_E (EE / 64)          /* 5000 */

/* ---------------- scratch (static device globals; no allocations) -------- */
__device__ float g_g1[NN * HH];   /* h[dst]-part of layer1 (+eb1)  */
__device__ float g_g2[NN * HH];   /* h[src]-part of layer1         */
__device__ float g_mi[NN * HH];   /* segment sum of mij*eij        */
__device__ float g_tmp[NN * HH];  /* node MLP hidden               */
__device__ float g_dx[NN * 3];    /* segment sum of rel_x*xg       */

/* XOR-swizzled transposed activation layout.
 * buf is a [K][64] tile stored as float4 groups: group g (4 rows) of feature k
 * lives at float4 index k*16 + (g ^ ((k>>2)&15)).
 * - GEMM A-reads: all lanes of a warp read the same address -> broadcast.
 * - transposed STS.128 (k = 4*tc+jj): addr4 mod 8 = (tr ^ tc) mod 8 -> conflict-free.
 */
__device__ __forceinline__ int sidx(int k, int r) {
    return (k * 16 + ((r >> 2) ^ ((k >> 2) & 15))) * 4 + (r & 3);
}

template<int KD>
__device__ __forceinline__ void gemm_acc(const float* __restrict__ As,
                                         const float* __restrict__ Bs,
                                         float acc[4][4], int tr, int tc) {
    const float4* A4 = (const float4*)As;
    const float4* B4 = (const float4*)Bs;
#pragma unroll 4
    for (int k = 0; k < KD; k++) {
        float4 a = A4[k * 16 + (tr ^ ((k >> 2) & 15))];
        float4 b = B4[k * 32 + tc];
        float av[4] = {a.x, a.y, a.z, a.w};
        float bv[4] = {b.x, b.y, b.z, b.w};
#pragma unroll
        for (int e = 0; e < 4; e++)
#pragma unroll
            for (int j = 0; j < 4; j++)
                acc[e][j] = fmaf(av[e], bv[j], acc[e][j]);
    }
}

__device__ __forceinline__ void store_T(float* __restrict__ buf,
                                        const float v[4][4], int tr, int tc) {
    float4* B4 = (float4*)buf;
#pragma unroll
    for (int jj = 0; jj < 4; jj++) {
        int k = 4 * tc + jj;
        B4[k * 16 + (tr ^ ((k >> 2) & 15))] =
            make_float4(v[0][jj], v[1][jj], v[2][jj], v[3][jj]);
    }
}

__device__ __forceinline__ void red4(float* p, float a, float b, float c, float d) {
    asm volatile("red.global.add.v4.f32 [%0], {%1,%2,%3,%4};"
                 :: "l"(p), "f"(a), "f"(b), "f"(c), "f"(d) : "memory");
}

/* ================= kernel A: per-node precompute + zero scratch ========== */
__global__ void __launch_bounds__(512, 1)
k_node_pre(const float* __restrict__ h, const float* __restrict__ ew1,
           const float* __restrict__ eb1) {
    extern __shared__ float sm[];
    float* W1 = sm;              /* ew1 rows  48..175 : 16384 */
    float* W2 = W1 + 16384;      /* ew1 rows 176..303 : 16384 */
    float* As = W2 + 16384;      /* h tile transposed :  8192 */
    int tid = threadIdx.x, tr = tid >> 5, tc = tid & 31;

    for (int i = tid; i < 16384; i += 512) {
        W1[i] = ew1[48 * 128 + i];
        W2[i] = ew1[176 * 128 + i];
    }
    int n0 = blockIdx.x * 64;
    for (int i = tid; i < 64 * 128; i += 512) {
        int r = i >> 7, k = i & 127, n = n0 + r;
        As[sidx(k, r)] = (n < NN) ? h[n * 128 + k] : 0.f;
    }
    /* zero mi / dx for this node tile (runs before edge kernel) */
    for (int i = tid; i < 64 * 128; i += 512) {
        int n = n0 + (i >> 7);
        if (n < NN) g_mi[n * 128 + (i & 127)] = 0.f;
    }
    if (tid < 192) {
        int n = n0 + tid / 3;
        if (n < NN) g_dx[n * 3 + tid % 3] = 0.f;
    }
    __syncthreads();

    float a1[4][4], a2[4][4];
#pragma unroll
    for (int e = 0; e < 4; e++)
#pragma unroll
        for (int j = 0; j < 4; j++) { a1[e][j] = eb1[4 * tc + j]; a2[e][j] = 0.f; }

    /* dual GEMM K=128 over the same A tile */
    {
        const float4* A4 = (const float4*)As;
        const float4* B14 = (const float4*)W1;
        const float4* B24 = (const float4*)W2;
#pragma unroll 4
        for (int k = 0; k < 128; k++) {
            float4 a = A4[k * 16 + (tr ^ ((k >> 2) & 15))];
            float4 b1 = B14[k * 32 + tc];
            float4 b2 = B24[k * 32 + tc];
            float av[4] = {a.x, a.y, a.z, a.w};
            float b1v[4] = {b1.x, b1.y, b1.z, b1.w};
            float b2v[4] = {b2.x, b2.y, b2.z, b2.w};
#pragma unroll
            for (int e = 0; e < 4; e++)
#pragma unroll
                for (int j = 0; j < 4; j++) {
                    a1[e][j] = fmaf(av[e], b1v[j], a1[e][j]);
                    a2[e][j] = fmaf(av[e], b2v[j], a2[e][j]);
                }
        }
    }
#pragma unroll
    for (int e = 0; e < 4; e++) {
        int n = n0 + tr * 4 + e;
        if (n < NN) {
            *(float4*)&g_g1[n * 128 + 4 * tc] =
                make_float4(a1[e][0], a1[e][1], a1[e][2], a1[e][3]);
            *(float4*)&g_g2[n * 128 + 4 * tc] =
                make_float4(a2[e][0], a2[e][1], a2[e][2], a2[e][3]);
        }
    }
}

/* ================= kernel B: fused edge pipeline (persistent) ============ */
__global__ void __launch_bounds__(512, 1)
k_edge(const float* __restrict__ x, const float* __restrict__ eattr,
       const float* __restrict__ ew1, const float* __restrict__ ew2,
       const float* __restrict__ eb2, const float* __restrict__ infw,
       const float* __restrict__ infb, const float* __restrict__ xw1,
       const float* __restrict__ xb1, const float* __restrict__ xw2,
       const float* __restrict__ xb2, const int* __restrict__ eidx) {
    extern __shared__ float sm[];
    float* Ws1  = sm;                 /* ew1 rows 0..47 : 6144  */
    float* Ws2  = Ws1 + 6144;         /* 16384 */
    float* Wx1  = Ws2 + 16384;        /* 16384 */
    float* winf = Wx1 + 16384;        /* 128 */
    float* wx2s = winf + 128;         /* 128 */
    float* eb2s = wx2s + 128;         /* 128 */
    float* xb1s = eb2s + 128;         /* 128 */
    float* bufX = xb1s + 128;         /* 8192 : As(48 rows) then Ms(128 rows) */
    float* bufY = bufX + 8192;        /* 8192 : Ts(128 rows) */
    float* relxs = bufY + 8192;       /* 192 */
    float* xl2s  = relxs + 192;       /* 64 */
    int*   dsts  = (int*)(xl2s + 64); /* 64 */
    int*   srcs  = dsts + 64;         /* 64 */

    int tid = threadIdx.x, tr = tid >> 5, tc = tid & 31;

    for (int i = tid; i < 6144; i += 512) Ws1[i] = ew1[i];
    for (int i = tid; i < 16384; i += 512) { Ws2[i] = ew2[i]; Wx1[i] = xw1[i]; }
    if (tid < 128) {
        winf[tid] = infw[tid]; wx2s[tid] = xw2[tid];
        eb2s[tid] = eb2[tid];  xb1s[tid] = xb1[tid];
    }
    __syncthreads();

    float wiv[4], wx2v[4], eb2r[4], xb1r[4];
#pragma unroll
    for (int j = 0; j < 4; j++) {
        wiv[j] = winf[4 * tc + j]; wx2v[j] = wx2s[4 * tc + j];
        eb2r[j] = eb2s[4 * tc + j]; xb1r[j] = xb1s[4 * tc + j];
    }
    const float infbv = infb[0];
    const float xb2v  = xb2[0];
    const float step  = 100.0f / 19.0f;
    const float coeff = -0.5f / (step * step);

    for (int tile = blockIdx.x; tile < NTILES_E; tile += gridDim.x) {
        __syncthreads();   /* prev-iteration readers done before overwrite */
        int e0 = tile * 64;

        if (tid < 64) {
            int e = e0 + tid;
            int d = eidx[e], s = eidx[EE + e];
            dsts[tid] = d; srcs[tid] = s;
            float rx = x[d * 3 + 0] - x[s * 3 + 0];
            float ry = x[d * 3 + 1] - x[s * 3 + 1];
            float rz = x[d * 3 + 2] - x[s * 3 + 2];
            relxs[tid * 3 + 0] = rx; relxs[tid * 3 + 1] = ry; relxs[tid * 3 + 2] = rz;
            xl2s[tid] = sqrtf(rx * rx + ry * ry + rz * rz);
        }
        for (int i = tid; i < 64 * 28; i += 512) {
            int e = i / 28, k = i - e * 28;
            bufX[sidx(k, e)] = eattr[(e0 + e) * 28 + k];
        }
        __syncthreads();   /* dsts/srcs/xl2 ready */

        for (int i = tid; i < 64 * 20; i += 512) {
            int e = i / 20, kk = i - e * 20;
            float dlt = xl2s[e] - (float)kk * step;
            bufX[sidx(28 + kk, e)] = expf(coeff * dlt * dlt);
        }
        /* gather precomputed node contributions (L2-resident) */
        float4 g1v[4], g2v[4];
#pragma unroll
        for (int e = 0; e < 4; e++) {
            int r = tr * 4 + e;
            g1v[e] = *(const float4*)&g_g1[dsts[r] * 128 + 4 * tc];
            g2v[e] = *(const float4*)&g_g2[srcs[r] * 128 + 4 * tc];
        }
        __syncthreads();   /* As (attr+rbf) complete */

        /* --- layer1: t1 = relu(attr_rbf@W1 + g1[dst] + g2[src]) --- */
        float acc[4][4];
#pragma unroll
        for (int e = 0; e < 4; e++)
#pragma unroll
            for (int j = 0; j < 4; j++) acc[e][j] = 0.f;
        gemm_acc<48>(bufX, Ws1, acc, tr, tc);
        {
            float t1[4][4];
#pragma unroll
            for (int e = 0; e < 4; e++) {
                float ga[4] = {g1v[e].x, g1v[e].y, g1v[e].z, g1v[e].w};
                float gb[4] = {g2v[e].x, g2v[e].y, g2v[e].z, g2v[e].w};
#pragma unroll
                for (int j = 0; j < 4; j++)
                    t1[e][j] = fmaxf(acc[e][j] + ga[j] + gb[j], 0.f);
            }
            store_T(bufY, t1, tr, tc);
        }
        __syncthreads();   /* Ts ready */

        /* --- layer2: mij = relu(t1@W2 + eb2) --- */
        float m[4][4];
#pragma unroll
        for (int e = 0; e < 4; e++)
#pragma unroll
            for (int j = 0; j < 4; j++) m[e][j] = eb2r[j];
        gemm_acc<128>(bufY, Ws2, m, tr, tc);
#pragma unroll
        for (int e = 0; e < 4; e++)
#pragma unroll
            for (int j = 0; j < 4; j++) m[e][j] = fmaxf(m[e][j], 0.f);

        /* edge gate eij = sigmoid(mij . inf_w + inf_b)  (warp allreduce) */
        float eij[4];
#pragma unroll
        for (int e = 0; e < 4; e++) {
            float p = m[e][0] * wiv[0] + m[e][1] * wiv[1] +
                      m[e][2] * wiv[2] + m[e][3] * wiv[3];
#pragma unroll
            for (int off = 16; off > 0; off >>= 1)
                p += __shfl_xor_sync(0xffffffffu, p, off);
            eij[e] = 1.f / (1.f + expf(-(p + infbv)));
        }
        /* scatter mi[dst] += mij*eij (vectorized reductions) */
#pragma unroll
        for (int e = 0; e < 4; e++) {
            float* p = &g_mi[dsts[tr * 4 + e] * 128 + 4 * tc];
            red4(p, m[e][0] * eij[e], m[e][1] * eij[e],
                    m[e][2] * eij[e], m[e][3] * eij[e]);
        }
        store_T(bufX, m, tr, tc);   /* Ms for x-MLP (all past GEMM1 by now) */
        __syncthreads();

        /* --- x-MLP: xg = relu(mij@xw1+xb1) . xw2 + xb2 --- */
        float u[4][4];
#pragma unroll
        for (int e = 0; e < 4; e++)
#pragma unroll
            for (int j = 0; j < 4; j++) u[e][j] = xb1r[j];
        gemm_acc<128>(bufX, Wx1, u, tr, tc);
#pragma unroll
        for (int e = 0; e < 4; e++) {
            float q = fmaxf(u[e][0], 0.f) * wx2v[0] + fmaxf(u[e][1], 0.f) * wx2v[1] +
                      fmaxf(u[e][2], 0.f) * wx2v[2] + fmaxf(u[e][3], 0.f) * wx2v[3];
#pragma unroll
            for (int off = 16; off > 0; off >>= 1)
                q += __shfl_xor_sync(0xffffffffu, q, off);
            float xg = q + xb2v;
            if (tc < 3) {
                int r = tr * 4 + e;
                atomicAdd(&g_dx[dsts[r] * 3 + tc], relxs[r * 3 + tc] * xg);
            }
        }
    }
}

/* ================= kernel C1: hidden = relu([mi,h]@nw1+nb1) ============== */
__global__ void __launch_bounds__(512, 1)
k_node1(const float* __restrict__ h, const float* __restrict__ nw1,
        const float* __restrict__ nb1) {
    extern __shared__ float sm[];
    float* W  = sm;            /* 32768 */
    float* As = W + 32768;     /* 16384 */
    int tid = threadIdx.x, tr = tid >> 5, tc = tid & 31;

    for (int i = tid; i < 32768; i += 512) W[i] = nw1[i];
    int n0 = blockIdx.x * 64;
    for (int i = tid; i < 64 * 256; i += 512) {
        int r = i >> 8, k = i & 255, n = n0 + r;
        float v = 0.f;
        if (n < NN) v = (k < 128) ? g_mi[n * 128 + k] : h[n * 128 + (k - 128)];
        As[sidx(k, r)] = v;
    }
    __syncthreads();

    float acc[4][4];
#pragma unroll
    for (int e = 0; e < 4; e++)
#pragma unroll
        for (int j = 0; j < 4; j++) acc[e][j] = nb1[4 * tc + j];
    gemm_acc<256>(As, W, acc, tr, tc);
#pragma unroll
    for (int e = 0; e < 4; e++) {
        int n = n0 + tr * 4 + e;
        if (n < NN)
            *(float4*)&g_tmp[n * 128 + 4 * tc] =
                make_float4(fmaxf(acc[e][0], 0.f), fmaxf(acc[e][1], 0.f),
                            fmaxf(acc[e][2], 0.f), fmaxf(acc[e][3], 0.f));
    }
}

/* ================= kernel C2: out = hidden@nw2+nb2 ======================= */
__global__ void __launch_bounds__(512, 1)
k_node2(const float* __restrict__ nw2, const float* __restrict__ nb2,
        float* __restrict__ out) {
    extern __shared__ float sm[];
    float* W  = sm;            /* 16384 */
    float* As = W + 16384;     /* 8192  */
    int tid = threadIdx.x, tr = tid >> 5, tc = tid & 31;

    for (int i = tid; i < 16384; i += 512) W[i] = nw2[i];
    int n0 = blockIdx.x * 64;
    for (int i = tid; i < 64 * 128; i += 512) {
        int r = i >> 7, k = i & 127, n = n0 + r;
        As[sidx(k, r)] = (n < NN) ? g_tmp[n * 128 + k] : 0.f;
    }
    __syncthreads();

    float acc[4][4];
#pragma unroll
    for (int e = 0; e < 4; e++)
#pragma unroll
        for (int j = 0; j < 4; j++) acc[e][j] = nb2[4 * tc + j];
    gemm_acc<128>(As, W, acc, tr, tc);
#pragma unroll
    for (int e = 0; e < 4; e++) {
        int n = n0 + tr * 4 + e;
        if (n < NN)
            *(float4*)&out[n * 128 + 4 * tc] =
                make_float4(acc[e][0], acc[e][1], acc[e][2], acc[e][3]);
    }
}

/* ================= kernel X: x_out = x + dx/E ============================ */
__global__ void k_xupd(const float* __restrict__ x, float* __restrict__ out) {
    int i = blockIdx.x * blockDim.x + threadIdx.x;
    if (i < NN * 3)
        out[NN * 128 + i] = x[i] + g_dx[i] * (1.0f / (float)EE);
}

/* ========================================================================= */
extern "C" void kernel_launch(void* const* d_in, const int* in_sizes, int n_in,
                              void* d_out, int out_size) {
    const float* h    = (const float*)d_in[0];
    const float* x    = (const float*)d_in[1];
    const float* ea   = (const float*)d_in[2];
    const float* ew1  = (const float*)d_in[3];
    const float* eb1  = (const float*)d_in[4];
    const float* ew2  = (const float*)d_in[5];
    const float* eb2  = (const float*)d_in[6];
    const float* infw = (const float*)d_in[7];
    const float* infb = (const float*)d_in[8];
    const float* nw1  = (const float*)d_in[9];
    const float* nb1  = (const float*)d_in[10];
    const float* nw2  = (const float*)d_in[11];
    const float* nb2  = (const float*)d_in[12];
    const float* xw1  = (const float*)d_in[13];
    const float* xb1  = (const float*)d_in[14];
    const float* xw2  = (const float*)d_in[15];
    const float* xb2  = (const float*)d_in[16];
    const int*   ei   = (const int*)d_in[17];
    float* out = (float*)d_out;

    const size_t smA  = (16384 + 16384 + 8192) * sizeof(float);          /* 163840 */
    const size_t smB  = (6144 + 16384 + 16384 + 512 + 8192 + 8192 +
                         192 + 64 + 128) * sizeof(float);                /* 224768 */
    const size_t smC1 = (32768 + 16384) * sizeof(float);                 /* 196608 */
    const size_t smC2 = (16384 + 8192) * sizeof(float);                  /*  98304 */

    cudaFuncSetAttribute(k_node_pre, cudaFuncAttributeMaxDynamicSharedMemorySize, (int)smA);
    cudaFuncSetAttribute(k_edge,     cudaFuncAttributeMaxDynamicSharedMemorySize, (int)smB);
    cudaFuncSetAttribute(k_node1,    cudaFuncAttributeMaxDynamicSharedMemorySize, (int)smC1);
    cudaFuncSetAttribute(k_node2,    cudaFuncAttributeMaxDynamicSharedMemorySize, (int)smC2);

    k_node_pre<<<NTILES_N, 512, smA>>>(h, ew1, eb1);
    k_edge<<<148, 512, smB>>>(x, ea, ew1, ew2, eb2, infw, infb,
                              xw1, xb1, xw2, xb2, ei);
    k_node1<<<NTILES_N, 512, smC1>>>(h, nw1, nb1);
    k_node2<<<NTILES_N, 512, smC2>>>(nw2, nb2, out);
    k_xupd<<<(NN * 3 + 255) / 256, 256>>>(x, out);
}

// round 7
// speedup vs baseline: 1.2121x; 1.2121x over previous
#include <cuda_runtime.h>
#include <math.h>
#include <stdint.h>

#define NN 20000
#define EE 320000
#define HH 128
#define NTILES_N ((NN + 63) / 64)   /* 313 */
#define ETILE 64
#define NTILES_E (EE / ETILE)       /* 5000 */

extern __shared__ char smraw[];

/* ---------------- scratch (static device globals; no allocations) -------- */
__device__ float g_g1[NN * HH];   /* h[dst]-part of layer1 (+eb1)  */
__device__ float g_g2[NN * HH];   /* h[src]-part of layer1         */
__device__ float g_mi[NN * HH];   /* segment sum of mij*eij        */
__device__ float g_tmp[NN * HH];  /* node MLP hidden               */
__device__ float g_dx[NN * 3];    /* segment sum of rel_x*xg       */

/* ---------------- packed f32x2 helpers ----------------------------------- */
typedef unsigned long long u64t;
__device__ __forceinline__ u64t dup2(float v) {
    u64t r; asm("mov.b64 %0,{%1,%1};" : "=l"(r) : "f"(v)); return r;
}
__device__ __forceinline__ u64t pk2(float a, float b) {
    u64t r; asm("mov.b64 %0,{%1,%2};" : "=l"(r) : "f"(a), "f"(b)); return r;
}
__device__ __forceinline__ void fma2(u64t& d, u64t a, u64t b) {
    asm("fma.rn.f32x2 %0,%1,%2,%0;" : "+l"(d) : "l"(a), "l"(b));
}
__device__ __forceinline__ void unp2(u64t v, float& a, float& b) {
    asm("mov.b64 {%0,%1},%2;" : "=f"(a), "=f"(b) : "l"(v));
}

__device__ __forceinline__ void red4(float* p, float a, float b, float c, float d) {
    asm volatile("red.global.add.v4.f32 [%0], {%1,%2,%3,%4};"
                 :: "l"(p), "f"(a), "f"(b), "f"(c), "f"(d) : "memory");
}

/* XOR-swizzled transposed activation layout (node kernels, 4-row groups):
 * float4 index = k*16 + ((r>>2) ^ ((k>>2)&15)), scalar = r&3  */
__device__ __forceinline__ int sidx(int k, int r) {
    return (k * 16 + ((r >> 2) ^ ((k >> 2) & 15))) * 4 + (r & 3);
}

/* ---- f32x2 GEMM for node kernels: acc[4 rows][4 cols], A pairs natural -- */
template<int KD>
__device__ __forceinline__ void gemm_acc_f2(const float* __restrict__ As,
                                            const float* __restrict__ Bs,
                                            float acc[4][4], int tr, int tc) {
    const float4* A4 = (const float4*)As;
    const float4* B4 = (const float4*)Bs;
    u64t a2[2][4];
#pragma unroll
    for (int j = 0; j < 4; j++) {
        a2[0][j] = pk2(acc[0][j], acc[1][j]);
        a2[1][j] = pk2(acc[2][j], acc[3][j]);
    }
#pragma unroll 4
    for (int k = 0; k < KD; k++) {
        ulonglong2 a = *(const ulonglong2*)(A4 + k * 16 + (tr ^ ((k >> 2) & 15)));
        float4 b = B4[k * 32 + tc];
        u64t b0 = dup2(b.x), b1 = dup2(b.y), b2 = dup2(b.z), b3 = dup2(b.w);
        fma2(a2[0][0], a.x, b0); fma2(a2[0][1], a.x, b1);
        fma2(a2[0][2], a.x, b2); fma2(a2[0][3], a.x, b3);
        fma2(a2[1][0], a.y, b0); fma2(a2[1][1], a.y, b1);
        fma2(a2[1][2], a.y, b2); fma2(a2[1][3], a.y, b3);
    }
#pragma unroll
    for (int j = 0; j < 4; j++) {
        unp2(a2[0][j], acc[0][j], acc[1][j]);
        unp2(a2[1][j], acc[2][j], acc[3][j]);
    }
}

/* ---- f32x2 GEMM for edge kernel: 8 edges (4 pairs) x 4 cols ------------- */
/* A layout: [K][64] edges; float4 chunk c=0..15, addr4 = k*16 + (c^((k>>2)&15)) */
template<int KD>
__device__ __forceinline__ void egemm(const float* __restrict__ As,
                                      const float* __restrict__ Bs,
                                      u64t accP[4][4], int rg, int cg) {
    const float4* A4 = (const float4*)As;
    const float4* B4 = (const float4*)Bs;
#pragma unroll 4
    for (int k = 0; k < KD; k++) {
        int sw = (k >> 2) & 15;
        ulonglong2 A0 = *(const ulonglong2*)(A4 + k * 16 + ((rg * 2) ^ sw));
        ulonglong2 A1 = *(const ulonglong2*)(A4 + k * 16 + ((rg * 2 + 1) ^ sw));
        float4 b = B4[k * 32 + cg];
        u64t b0 = dup2(b.x), b1 = dup2(b.y), b2 = dup2(b.z), b3 = dup2(b.w);
        fma2(accP[0][0], A0.x, b0); fma2(accP[0][1], A0.x, b1);
        fma2(accP[0][2], A0.x, b2); fma2(accP[0][3], A0.x, b3);
        fma2(accP[1][0], A0.y, b0); fma2(accP[1][1], A0.y, b1);
        fma2(accP[1][2], A0.y, b2); fma2(accP[1][3], A0.y, b3);
        fma2(accP[2][0], A1.x, b0); fma2(accP[2][1], A1.x, b1);
        fma2(accP[2][2], A1.x, b2); fma2(accP[2][3], A1.x, b3);
        fma2(accP[3][0], A1.y, b0); fma2(accP[3][1], A1.y, b1);
        fma2(accP[3][2], A1.y, b2); fma2(accP[3][3], A1.y, b3);
    }
}

/* ================= kernel A: per-node precompute + zero scratch ========== */
__global__ void __launch_bounds__(512, 1)
k_node_pre(const float* __restrict__ h, const float* __restrict__ ew1,
           const float* __restrict__ eb1) {
    float* sm = (float*)smraw;
    float* W1 = sm;              /* ew1 rows  48..175 : 16384 */
    float* W2 = W1 + 16384;      /* ew1 rows 176..303 : 16384 */
    float* As = W2 + 16384;      /* h tile transposed :  8192 */
    int tid = threadIdx.x, tr = tid >> 5, tc = tid & 31;

    for (int i = tid; i < 16384; i += 512) {
        W1[i] = ew1[48 * 128 + i];
        W2[i] = ew1[176 * 128 + i];
    }
    int n0 = blockIdx.x * 64;
    for (int i = tid; i < 64 * 128; i += 512) {
        int r = i >> 7, k = i & 127, n = n0 + r;
        As[sidx(k, r)] = (n < NN) ? h[n * 128 + k] : 0.f;
    }
    for (int i = tid; i < 64 * 128; i += 512) {
        int n = n0 + (i >> 7);
        if (n < NN) g_mi[n * 128 + (i & 127)] = 0.f;
    }
    if (tid < 192) {
        int n = n0 + tid / 3;
        if (n < NN) g_dx[n * 3 + tid % 3] = 0.f;
    }
    __syncthreads();

    float a1[4][4], a2[4][4];
#pragma unroll
    for (int e = 0; e < 4; e++)
#pragma unroll
        for (int j = 0; j < 4; j++) { a1[e][j] = eb1[4 * tc + j]; a2[e][j] = 0.f; }
    gemm_acc_f2<128>(As, W1, a1, tr, tc);
    gemm_acc_f2<128>(As, W2, a2, tr, tc);
#pragma unroll
    for (int e = 0; e < 4; e++) {
        int n = n0 + tr * 4 + e;
        if (n < NN) {
            *(float4*)&g_g1[n * 128 + 4 * tc] =
                make_float4(a1[e][0], a1[e][1], a1[e][2], a1[e][3]);
            *(float4*)&g_g2[n * 128 + 4 * tc] =
                make_float4(a2[e][0], a2[e][1], a2[e][2], a2[e][3]);
        }
    }
}

/* ================= kernel B: fused edge pipeline (persistent, f32x2) ===== */
/* smem float offsets */
#define SE_DST  0
#define SE_SRC  64
#define SE_RELX 128
#define SE_XL2  320
#define SE_EB2  384
#define SE_XB1  512
#define SE_INFW 640
#define SE_XW2  768
#define SE_BUFF 896     /* feat48 rows then Ms (128 rows) : 8192 */
#define SE_BUFT 9088    /* t1 : 8192 */
#define SE_WS1  17280   /* 6144 */
#define SE_WS2  23424   /* 16384 */
#define SE_WX1  39808   /* 16384 */
#define SE_TOTAL 56192  /* floats -> 224768 bytes */

__global__ void __launch_bounds__(256, 1)
k_edge(const float* __restrict__ x, const float* __restrict__ eattr,
       const float* __restrict__ ew1, const float* __restrict__ ew2,
       const float* __restrict__ eb2, const float* __restrict__ infw,
       const float* __restrict__ infb, const float* __restrict__ xw1,
       const float* __restrict__ xb1, const float* __restrict__ xw2,
       const float* __restrict__ xb2, const int* __restrict__ eidx) {
    float* sm = (float*)smraw;
    int* dsts = (int*)sm;
    int* srcs = dsts + 64;
    float* relxs = sm + SE_RELX;
    float* xl2s  = sm + SE_XL2;
    float* eb2s  = sm + SE_EB2;
    float* xb1s  = sm + SE_XB1;
    float* infws = sm + SE_INFW;
    float* xw2s  = sm + SE_XW2;
    float* bufF  = sm + SE_BUFF;
    float* bufT  = sm + SE_BUFT;
    float* Ws1   = sm + SE_WS1;
    float* Ws2   = sm + SE_WS2;
    float* Wx1   = sm + SE_WX1;

    int tid = threadIdx.x, rg = tid >> 5, cg = tid & 31;

    for (int i = tid; i < 6144; i += 256) Ws1[i] = ew1[i];
    for (int i = tid; i < 16384; i += 256) { Ws2[i] = ew2[i]; Wx1[i] = xw1[i]; }
    if (tid < 128) {
        eb2s[tid] = eb2[tid]; xb1s[tid] = xb1[tid];
        infws[tid] = infw[tid]; xw2s[tid] = xw2[tid];
    }
    __syncthreads();

    float eb2r[4], infwr[4], xb1r[4], xw2r[4];
#pragma unroll
    for (int j = 0; j < 4; j++) {
        eb2r[j] = eb2s[cg * 4 + j]; infwr[j] = infws[cg * 4 + j];
        xb1r[j] = xb1s[cg * 4 + j]; xw2r[j] = xw2s[cg * 4 + j];
    }
    const float infbv = infb[0];
    const float xb2v  = xb2[0];
    const float step  = 100.0f / 19.0f;
    const float coeff = -0.5f / (step * step);

    for (int tile = blockIdx.x; tile < NTILES_E; tile += gridDim.x) {
        __syncthreads();   /* prev-iteration readers done before overwrite */
        int e0 = tile * ETILE;

        if (tid < 64) {
            int e = e0 + tid;
            int d = eidx[e], s = eidx[EE + e];
            dsts[tid] = d; srcs[tid] = s;
            float rx = x[d * 3 + 0] - x[s * 3 + 0];
            float ry = x[d * 3 + 1] - x[s * 3 + 1];
            float rz = x[d * 3 + 2] - x[s * 3 + 2];
            relxs[tid * 3 + 0] = rx; relxs[tid * 3 + 1] = ry; relxs[tid * 3 + 2] = rz;
            xl2s[tid] = sqrtf(rx * rx + ry * ry + rz * rz);
        }
        for (int i = tid; i < 64 * 28; i += 256) {
            int e = i / 28, k = i - 28 * e;
            bufF[(k * 16 + ((e >> 2) ^ ((k >> 2) & 15))) * 4 + (e & 3)] =
                eattr[(size_t)(e0 + e) * 28 + k];
        }
        __syncthreads();   /* dsts/srcs/xl2 ready */

        for (int i = tid; i < 64 * 20; i += 256) {
            int e = i / 20, kk = i - 20 * e;
            float dl = xl2s[e] - (float)kk * step;
            int k = 28 + kk;
            bufF[(k * 16 + ((e >> 2) ^ ((k >> 2) & 15))) * 4 + (e & 3)] =
                expf(coeff * dl * dl);
        }
        /* gather precomputed node contributions (L2-resident) */
        int dr[8];
        float4 gA[8], gB[8];
#pragma unroll
        for (int e = 0; e < 8; e++) {
            int d_ = dsts[rg * 8 + e], s_ = srcs[rg * 8 + e];
            dr[e] = d_;
            gA[e] = *(const float4*)&g_g1[(size_t)d_ * 128 + cg * 4];
            gB[e] = *(const float4*)&g_g2[(size_t)s_ * 128 + cg * 4];
        }
        __syncthreads();   /* feat complete */

        /* --- GEMM1: acc = feat48 @ W1 --- */
        u64t accP[4][4];
#pragma unroll
        for (int p = 0; p < 4; p++)
#pragma unroll
            for (int j = 0; j < 4; j++) accP[p][j] = 0ull;
        egemm<48>(bufF, Ws1, accP, rg, cg);

        /* ep1: t1 = relu(acc + g1[dst] + g2[src]) -> bufT transposed */
        float vlo[4][4], vhi[4][4];
#pragma unroll
        for (int p = 0; p < 4; p++) {
            float4 a0 = gA[2 * p], b0 = gB[2 * p];
            float4 a1 = gA[2 * p + 1], b1 = gB[2 * p + 1];
            float aa0[4] = {a0.x, a0.y, a0.z, a0.w};
            float bb0[4] = {b0.x, b0.y, b0.z, b0.w};
            float aa1[4] = {a1.x, a1.y, a1.z, a1.w};
            float bb1[4] = {b1.x, b1.y, b1.z, b1.w};
#pragma unroll
            for (int j = 0; j < 4; j++) {
                float lo, hi; unp2(accP[p][j], lo, hi);
                vlo[p][j] = fmaxf(lo + aa0[j] + bb0[j], 0.f);
                vhi[p][j] = fmaxf(hi + aa1[j] + bb1[j], 0.f);
            }
        }
        {
            float4* T4 = (float4*)bufT;
#pragma unroll
            for (int j = 0; j < 4; j++) {
                int kp = cg * 4 + j, sw = (kp >> 2) & 15;
                ulonglong2 w0, w1;
                w0.x = pk2(vlo[0][j], vhi[0][j]); w0.y = pk2(vlo[1][j], vhi[1][j]);
                w1.x = pk2(vlo[2][j], vhi[2][j]); w1.y = pk2(vlo[3][j], vhi[3][j]);
                *(ulonglong2*)(T4 + kp * 16 + ((rg * 2) ^ sw))     = w0;
                *(ulonglong2*)(T4 + kp * 16 + ((rg * 2 + 1) ^ sw)) = w1;
            }
        }
        __syncthreads();   /* t1 ready */

        /* --- GEMM2: mij = relu(t1 @ W2 + eb2) --- */
#pragma unroll
        for (int p = 0; p < 4; p++)
#pragma unroll
            for (int j = 0; j < 4; j++) accP[p][j] = dup2(eb2r[j]);
        egemm<128>(bufT, Ws2, accP, rg, cg);

        /* ep2: relu, gate dot, scatter mi, store Ms */
#pragma unroll
        for (int p = 0; p < 4; p++)
#pragma unroll
            for (int j = 0; j < 4; j++) {
                float lo, hi; unp2(accP[p][j], lo, hi);
                vlo[p][j] = fmaxf(lo, 0.f); vhi[p][j] = fmaxf(hi, 0.f);
            }
        float pd[8];
#pragma unroll
        for (int p = 0; p < 4; p++) {
            pd[2 * p]     = vlo[p][0] * infwr[0] + vlo[p][1] * infwr[1]
                          + vlo[p][2] * infwr[2] + vlo[p][3] * infwr[3];
            pd[2 * p + 1] = vhi[p][0] * infwr[0] + vhi[p][1] * infwr[1]
                          + vhi[p][2] * infwr[2] + vhi[p][3] * infwr[3];
        }
#pragma unroll
        for (int o = 16; o > 0; o >>= 1)
#pragma unroll
            for (int e = 0; e < 8; e++)
                pd[e] += __shfl_xor_sync(0xffffffffu, pd[e], o);
        float eij[8];
#pragma unroll
        for (int e = 0; e < 8; e++)
            eij[e] = 1.f / (1.f + expf(-(pd[e] + infbv)));
#pragma unroll
        for (int p = 0; p < 4; p++) {
            float el = eij[2 * p], eh = eij[2 * p + 1];
            red4(&g_mi[(size_t)dr[2 * p] * 128 + cg * 4],
                 vlo[p][0] * el, vlo[p][1] * el, vlo[p][2] * el, vlo[p][3] * el);
            red4(&g_mi[(size_t)dr[2 * p + 1] * 128 + cg * 4],
                 vhi[p][0] * eh, vhi[p][1] * eh, vhi[p][2] * eh, vhi[p][3] * eh);
        }
        {
            float4* F4 = (float4*)bufF;
#pragma unroll
            for (int j = 0; j < 4; j++) {
                int kp = cg * 4 + j, sw = (kp >> 2) & 15;
                ulonglong2 w0, w1;
                w0.x = pk2(vlo[0][j], vhi[0][j]); w0.y = pk2(vlo[1][j], vhi[1][j]);
                w1.x = pk2(vlo[2][j], vhi[2][j]); w1.y = pk2(vlo[3][j], vhi[3][j]);
                *(ulonglong2*)(F4 + kp * 16 + ((rg * 2) ^ sw))     = w0;
                *(ulonglong2*)(F4 + kp * 16 + ((rg * 2 + 1) ^ sw)) = w1;
            }
        }
        __syncthreads();   /* Ms ready */

        /* --- GEMM3: u = mij @ xw1 + xb1 --- */
#pragma unroll
        for (int p = 0; p < 4; p++)
#pragma unroll
            for (int j = 0; j < 4; j++) accP[p][j] = dup2(xb1r[j]);
        egemm<128>(bufF, Wx1, accP, rg, cg);

        /* ep3: xg = relu(u).xw2 + xb2 ; scatter dx */
        float q[8];
#pragma unroll
        for (int p = 0; p < 4; p++) {
            float qlo = 0.f, qhi = 0.f;
#pragma unroll
            for (int j = 0; j < 4; j++) {
                float lo, hi; unp2(accP[p][j], lo, hi);
                qlo += fmaxf(lo, 0.f) * xw2r[j];
                qhi += fmaxf(hi, 0.f) * xw2r[j];
            }
            q[2 * p] = qlo; q[2 * p + 1] = qhi;
        }
#pragma unroll
        for (int o = 16; o > 0; o >>= 1)
#pragma unroll
            for (int e = 0; e < 8; e++)
                q[e] += __shfl_xor_sync(0xffffffffu, q[e], o);
        if (cg < 3) {
#pragma unroll
            for (int e = 0; e < 8; e++) {
                float xg = q[e] + xb2v;
                atomicAdd(&g_dx[dr[e] * 3 + cg],
                          relxs[(rg * 8 + e) * 3 + cg] * xg);
            }
        }
    }
}

/* ================= kernel C1: hidden = relu([mi,h]@nw1+nb1) ============== */
__global__ void __launch_bounds__(512, 1)
k_node1(const float* __restrict__ h, const float* __restrict__ nw1,
        const float* __restrict__ nb1) {
    float* sm = (float*)smraw;
    float* W  = sm;            /* 32768 */
    float* As = W + 32768;     /* 16384 */
    int tid = threadIdx.x, tr = tid >> 5, tc = tid & 31;

    for (int i = tid; i < 32768; i += 512) W[i] = nw1[i];
    int n0 = blockIdx.x * 64;
    for (int i = tid; i < 64 * 256; i += 512) {
        int r = i >> 8, k = i & 255, n = n0 + r;
        float v = 0.f;
        if (n < NN) v = (k < 128) ? g_mi[n * 128 + k] : h[n * 128 + (k - 128)];
        As[sidx(k, r)] = v;
    }
    __syncthreads();

    float acc[4][4];
#pragma unroll
    for (int e = 0; e < 4; e++)
#pragma unroll
        for (int j = 0; j < 4; j++) acc[e][j] = nb1[4 * tc + j];
    gemm_acc_f2<256>(As, W, acc, tr, tc);
#pragma unroll
    for (int e = 0; e < 4; e++) {
        int n = n0 + tr * 4 + e;
        if (n < NN)
            *(float4*)&g_tmp[n * 128 + 4 * tc] =
                make_float4(fmaxf(acc[e][0], 0.f), fmaxf(acc[e][1], 0.f),
                            fmaxf(acc[e][2], 0.f), fmaxf(acc[e][3], 0.f));
    }
}

/* ================= kernel C2: out = hidden@nw2+nb2 ======================= */
__global__ void __launch_bounds__(512, 1)
k_node2(const float* __restrict__ nw2, const float* __restrict__ nb2,
        float* __restrict__ out) {
    float* sm = (float*)smraw;
    float* W  = sm;            /* 16384 */
    float* As = W + 16384;     /* 8192  */
    int tid = threadIdx.x, tr = tid >> 5, tc = tid & 31;

    for (int i = tid; i < 16384; i += 512) W[i] = nw2[i];
    int n0 = blockIdx.x * 64;
    for (int i = tid; i < 64 * 128; i += 512) {
        int r = i >> 7, k = i & 127, n = n0 + r;
        As[sidx(k, r)] = (n < NN) ? g_tmp[n * 128 + k] : 0.f;
    }
    __syncthreads();

    float acc[4][4];
#pragma unroll
    for (int e = 0; e < 4; e++)
#pragma unroll
        for (int j = 0; j < 4; j++) acc[e][j] = nb2[4 * tc + j];
    gemm_acc_f2<128>(As, W, acc, tr, tc);
#pragma unroll
    for (int e = 0; e < 4; e++) {
        int n = n0 + tr * 4 + e;
        if (n < NN)
            *(float4*)&out[n * 128 + 4 * tc] =
                make_float4(acc[e][0], acc[e][1], acc[e][2], acc[e][3]);
    }
}

/* ================= kernel X: x_out = x + dx/E ============================ */
__global__ void k_xupd(const float* __restrict__ x, float* __restrict__ out) {
    int i = blockIdx.x * blockDim.x + threadIdx.x;
    if (i < NN * 3)
        out[NN * 128 + i] = x[i] + g_dx[i] * (1.0f / (float)EE);
}

/* ========================================================================= */
extern "C" void kernel_launch(void* const* d_in, const int* in_sizes, int n_in,
                              void* d_out, int out_size) {
    const float* h    = (const float*)d_in[0];
    const float* x    = (const float*)d_in[1];
    const float* ea   = (const float*)d_in[2];
    const float* ew1  = (const float*)d_in[3];
    const float* eb1  = (const float*)d_in[4];
    const float* ew2  = (const float*)d_in[5];
    const float* eb2  = (const float*)d_in[6];
    const float* infw = (const float*)d_in[7];
    const float* infb = (const float*)d_in[8];
    const float* nw1  = (const float*)d_in[9];
    const float* nb1  = (const float*)d_in[10];
    const float* nw2  = (const float*)d_in[11];
    const float* nb2  = (const float*)d_in[12];
    const float* xw1  = (const float*)d_in[13];
    const float* xb1  = (const float*)d_in[14];
    const float* xw2  = (const float*)d_in[15];
    const float* xb2  = (const float*)d_in[16];
    const int*   ei   = (const int*)d_in[17];
    float* out = (float*)d_out;

    const size_t smA  = (16384 + 16384 + 8192) * sizeof(float);   /* 163840 */
    const size_t smB  = SE_TOTAL * sizeof(float);                 /* 224768 */
    const size_t smC1 = (32768 + 16384) * sizeof(float);          /* 196608 */
    const size_t smC2 = (16384 + 8192) * sizeof(float);           /*  98304 */

    cudaFuncSetAttribute(k_node_pre, cudaFuncAttributeMaxDynamicSharedMemorySize, (int)smA);
    cudaFuncSetAttribute(k_edge,     cudaFuncAttributeMaxDynamicSharedMemorySize, (int)smB);
    cudaFuncSetAttribute(k_node1,    cudaFuncAttributeMaxDynamicSharedMemorySize, (int)smC1);
    cudaFuncSetAttribute(k_node2,    cudaFuncAttributeMaxDynamicSharedMemorySize, (int)smC2);

    k_node_pre<<<NTILES_N, 512, smA>>>(h, ew1, eb1);
    k_edge<<<148, 256, smB>>>(x, ea, ew1, ew2, eb2, infw, infb,
                              xw1, xb1, xw2, xb2, ei);
    k_node1<<<NTILES_N, 512, smC1>>>(h, nw1, nb1);
    k_node2<<<NTILES_N, 512, smC2>>>(nw2, nb2, out);
    k_xupd<<<(NN * 3 + 255) / 256, 256>>>(x, out);
}

// round 8
// speedup vs baseline: 1.9604x; 1.6173x over previous
#include <cuda_runtime.h>
#include <cuda_bf16.h>
#include <math.h>
#include <stdint.h>

#define NN 20000
#define EE 320000
#define HH 128
#define NTILES_N ((NN + 63) / 64)   /* 313 */
#define ETILE 64
#define NTILES_E (EE / ETILE)       /* 5000 */

extern __shared__ char smraw[];

/* ---------------- scratch (static device globals; no allocations) -------- */
__device__ float g_g1[NN * HH];   /* h[dst]-part of layer1 (+eb1)  */
__device__ float g_g2[NN * HH];   /* h[src]-part of layer1         */
__device__ float g_mi[NN * HH];   /* segment sum of mij*eij        */
__device__ float g_tmp[NN * HH];  /* node MLP hidden               */
__device__ float g_dx[NN * 3];    /* segment sum of rel_x*xg       */

/* ---------------- small helpers ------------------------------------------ */
typedef unsigned long long u64t;
__device__ __forceinline__ u64t dup2(float v) {
    u64t r; asm("mov.b64 %0,{%1,%1};" : "=l"(r) : "f"(v)); return r;
}
__device__ __forceinline__ u64t pk2(float a, float b) {
    u64t r; asm("mov.b64 %0,{%1,%2};" : "=l"(r) : "f"(a), "f"(b)); return r;
}
__device__ __forceinline__ void fma2(u64t& d, u64t a, u64t b) {
    asm("fma.rn.f32x2 %0,%1,%2,%0;" : "+l"(d) : "l"(a), "l"(b));
}
__device__ __forceinline__ void unp2(u64t v, float& a, float& b) {
    asm("mov.b64 {%0,%1},%2;" : "=f"(a), "=f"(b) : "l"(v));
}
__device__ __forceinline__ void red4(float* p, float a, float b, float c, float d) {
    asm volatile("red.global.add.v4.f32 [%0], {%1,%2,%3,%4};"
                 :: "l"(p), "f"(a), "f"(b), "f"(c), "f"(d) : "memory");
}
__device__ __forceinline__ uint32_t smem_u32(const void* p) {
    uint32_t a;
    asm("{ .reg .u64 t; cvta.to.shared.u64 t, %1; cvt.u32.u64 %0, t; }"
        : "=r"(a) : "l"(p));
    return a;
}
/* pack (low half = a, high half = b) */
#define PACKBF2(res, a, b) \
    asm("cvt.rn.satfinite.bf16x2.f32 %0, %1, %2;" : "=r"(res) : "f"(b), "f"(a))
__device__ __forceinline__ void split2(float a0, float a1, uint32_t& hw, uint32_t& lw) {
    PACKBF2(hw, a0, a1);
    float h0 = __uint_as_float(hw << 16);
    float h1 = __uint_as_float(hw & 0xffff0000u);
    PACKBF2(lw, a0 - h0, a1 - h1);
}

/* ---------------- mma / ldmatrix ----------------------------------------- */
#define LDSM4(r, a) \
    asm volatile("ldmatrix.sync.aligned.m8n8.x4.shared.b16 {%0,%1,%2,%3},[%4];" \
        : "=r"((r)[0]), "=r"((r)[1]), "=r"((r)[2]), "=r"((r)[3]) : "r"(a))
#define MMA_B16(d, a, b0, b1) \
    asm volatile("mma.sync.aligned.m16n8k16.row.col.f32.bf16.bf16.f32 " \
        "{%0,%1,%2,%3},{%4,%5,%6,%7},{%8,%9},{%0,%1,%2,%3};" \
        : "+f"((d)[0]), "+f"((d)[1]), "+f"((d)[2]), "+f"((d)[3]) \
        : "r"((a)[0]), "r"((a)[1]), "r"((a)[2]), "r"((a)[3]), "r"(b0), "r"(b1))

/* XOR-swizzled bf16 tile: row r, 16B chunk c -> phys chunk (c&~7)|((c&7)^(r&7)) */
__device__ __forceinline__ uint32_t pch(int c, int r) {
    return (uint32_t)((c & ~7) | ((c & 7) ^ (r & 7)));
}

/* generic warp GEMM: D[16 edges x 64 cols] += A[16xK] * B[K x 64]^T          */
template<int KSTEPS, bool X3, int CA, int CB>
__device__ __forceinline__ void mma_gemm(const char* aH, const char* aL,
                                         const char* bH, const char* bL,
                                         float acc[8][4], int wm, int wn, int lane) {
    int ar7 = lane & 7;
    int arow = 16 * wm + ((lane >> 3) & 1) * 8 + ar7;
    int acoff = lane >> 4;
    int brow_l = ((lane >> 4) & 1) * 8 + ar7;
    int bcoff = (lane >> 3) & 1;
    uint32_t aHb = smem_u32(aH) + (uint32_t)(arow * CA);
    uint32_t aLb = X3 ? (smem_u32(aL) + (uint32_t)(arow * CA)) : 0u;
    uint32_t bHb = smem_u32(bH);
    uint32_t bLb = X3 ? smem_u32(bL) : 0u;
#pragma unroll
    for (int ks = 0; ks < KSTEPS; ks++) {
        uint32_t aoff = pch(2 * ks + acoff, ar7) * 16;
        uint32_t ah[4], al[4];
        LDSM4(ah, aHb + aoff);
        if (X3) LDSM4(al, aLb + aoff);
        uint32_t boff = pch(2 * ks + bcoff, ar7) * 16;
#pragma unroll
        for (int jp = 0; jp < 4; jp++) {
            uint32_t brb = (uint32_t)((wn * 64 + jp * 16 + brow_l) * CB) + boff;
            uint32_t bh[4];
            LDSM4(bh, bHb + brb);
            MMA_B16(acc[2 * jp],     ah, bh[0], bh[1]);
            MMA_B16(acc[2 * jp + 1], ah, bh[2], bh[3]);
            if (X3) {
                uint32_t bl[4];
                LDSM4(bl, bLb + brb);
                MMA_B16(acc[2 * jp],     al, bh[0], bh[1]);
                MMA_B16(acc[2 * jp + 1], al, bh[2], bh[3]);
                MMA_B16(acc[2 * jp],     ah, bl[0], bl[1]);
                MMA_B16(acc[2 * jp + 1], ah, bl[2], bl[3]);
            }
        }
    }
}

/* stage D fragments -> fp32 smem [64][128], 16B-chunk swizzled (512B rows)   */
__device__ __forceinline__ void stage_D(char* DS, const float acc[8][4],
                                        int wm, int wn, int lane) {
    int r0 = 16 * wm + (lane >> 2);
    int r1 = r0 + 8;
    int cbase = wn * 64 + 2 * (lane & 3);
#pragma unroll
    for (int j = 0; j < 8; j++) {
        int cc = cbase + 8 * j;
        int ch = cc >> 2, inoff = (cc & 3) * 4;
        *(float2*)(DS + r0 * 512 + pch(ch, r0) * 16 + inoff) =
            make_float2(acc[j][0], acc[j][1]);
        *(float2*)(DS + r1 * 512 + pch(ch, r1) * 16 + inoff) =
            make_float2(acc[j][2], acc[j][3]);
    }
}

/* XOR-swizzled transposed activation layout (node kernels) */
__device__ __forceinline__ int sidx(int k, int r) {
    return (k * 16 + ((r >> 2) ^ ((k >> 2) & 15))) * 4 + (r & 3);
}
template<int KD>
__device__ __forceinline__ void gemm_acc_f2(const float* __restrict__ As,
                                            const float* __restrict__ Bs,
                                            float acc[4][4], int tr, int tc) {
    const float4* A4 = (const float4*)As;
    const float4* B4 = (const float4*)Bs;
    u64t a2[2][4];
#pragma unroll
    for (int j = 0; j < 4; j++) {
        a2[0][j] = pk2(acc[0][j], acc[1][j]);
        a2[1][j] = pk2(acc[2][j], acc[3][j]);
    }
#pragma unroll 4
    for (int k = 0; k < KD; k++) {
        ulonglong2 a = *(const ulonglong2*)(A4 + k * 16 + (tr ^ ((k >> 2) & 15)));
        float4 b = B4[k * 32 + tc];
        u64t b0 = dup2(b.x), b1 = dup2(b.y), b2 = dup2(b.z), b3 = dup2(b.w);
        fma2(a2[0][0], a.x, b0); fma2(a2[0][1], a.x, b1);
        fma2(a2[0][2], a.x, b2); fma2(a2[0][3], a.x, b3);
        fma2(a2[1][0], a.y, b0); fma2(a2[1][1], a.y, b1);
        fma2(a2[1][2], a.y, b2); fma2(a2[1][3], a.y, b3);
    }
#pragma unroll
    for (int j = 0; j < 4; j++) {
        unp2(a2[0][j], acc[0][j], acc[1][j]);
        unp2(a2[1][j], acc[2][j], acc[3][j]);
    }
}

/* ================= kernel A: per-node precompute + zero scratch ========== */
__global__ void __launch_bounds__(512, 1)
k_node_pre(const float* __restrict__ h, const float* __restrict__ ew1,
           const float* __restrict__ eb1) {
    float* sm = (float*)smraw;
    float* W1 = sm;
    float* W2 = W1 + 16384;
    float* As = W2 + 16384;
    int tid = threadIdx.x, tr = tid >> 5, tc = tid & 31;

    for (int i = tid; i < 16384; i += 512) {
        W1[i] = ew1[48 * 128 + i];
        W2[i] = ew1[176 * 128 + i];
    }
    int n0 = blockIdx.x * 64;
    for (int i = tid; i < 64 * 128; i += 512) {
        int r = i >> 7, k = i & 127, n = n0 + r;
        As[sidx(k, r)] = (n < NN) ? h[n * 128 + k] : 0.f;
    }
    for (int i = tid; i < 64 * 128; i += 512) {
        int n = n0 + (i >> 7);
        if (n < NN) g_mi[n * 128 + (i & 127)] = 0.f;
    }
    if (tid < 192) {
        int n = n0 + tid / 3;
        if (n < NN) g_dx[n * 3 + tid % 3] = 0.f;
    }
    __syncthreads();

    float a1[4][4], a2[4][4];
#pragma unroll
    for (int e = 0; e < 4; e++)
#pragma unroll
        for (int j = 0; j < 4; j++) { a1[e][j] = eb1[4 * tc + j]; a2[e][j] = 0.f; }
    gemm_acc_f2<128>(As, W1, a1, tr, tc);
    gemm_acc_f2<128>(As, W2, a2, tr, tc);
#pragma unroll
    for (int e = 0; e < 4; e++) {
        int n = n0 + tr * 4 + e;
        if (n < NN) {
            *(float4*)&g_g1[n * 128 + 4 * tc] =
                make_float4(a1[e][0], a1[e][1], a1[e][2], a1[e][3]);
            *(float4*)&g_g2[n * 128 + 4 * tc] =
                make_float4(a2[e][0], a2[e][1], a2[e][2], a2[e][3]);
        }
    }
}

/* ================= kernel B: mma.sync bf16 edge pipeline ================= */
/* smem byte offsets */
#define SB_DST   0
#define SB_SRC   256
#define SB_RELX  512
#define SB_XL2   1280
#define SB_EB2   1536
#define SB_XB1   2048
#define SB_INFW  2560
#define SB_XW2   3072
#define SB_FEATH 4096           /* [64][64] bf16 : 8192  (also bufM lower) */
#define SB_FEATL 12288          /* [64][64] bf16 : 8192  (also bufM upper) */
#define SB_BUFM  4096           /* [64][128] bf16 : 16384 (reuses feat)    */
#define SB_TH    20480          /* t1 hi [64][128] bf16 : 16384 */
#define SB_TL    36864          /* t1 lo : 16384 */
#define SB_DS    53248          /* D stage [64][128] f32 : 32768 */
#define SB_W1H   86016          /* [128][64] bf16 : 16384 */
#define SB_W1L   102400
#define SB_W2H   118784         /* [128][128] bf16 : 32768 */
#define SB_W2L   151552
#define SB_W3H   184320
#define SB_TOTAL 217088

__global__ void __launch_bounds__(256, 1)
k_edge(const float* __restrict__ x, const float* __restrict__ eattr,
       const float* __restrict__ ew1, const float* __restrict__ ew2,
       const float* __restrict__ eb2, const float* __restrict__ infw,
       const float* __restrict__ infb, const float* __restrict__ xw1,
       const float* __restrict__ xb1, const float* __restrict__ xw2,
       const float* __restrict__ xb2, const int* __restrict__ eidx) {
    char* sm = smraw;
    int* dsts = (int*)(sm + SB_DST);
    int* srcs = (int*)(sm + SB_SRC);
    float* relxs = (float*)(sm + SB_RELX);
    float* xl2s  = (float*)(sm + SB_XL2);
    float* eb2s  = (float*)(sm + SB_EB2);
    float* xb1s  = (float*)(sm + SB_XB1);
    float* infws = (float*)(sm + SB_INFW);
    float* xw2s  = (float*)(sm + SB_XW2);

    int tid = threadIdx.x;
    int lane = tid & 31;
    int wid = tid >> 5;
    int wm = wid >> 1, wn = wid & 1;
    int rg = wid, cg = lane;          /* epilogue row layout: 8 edges x 4 cols */

    /* ---- one-time: weights -> swizzled bf16 hi/lo smem tiles ---- */
    for (int i = tid; i < 128 * 64; i += 256) {
        int n = i >> 6, k = i & 63;
        float v = (k < 48) ? ew1[k * 128 + n] : 0.f;
        __nv_bfloat16 hb = __float2bfloat16(v);
        uint32_t off = (uint32_t)(n * 128) + pch(k >> 3, n) * 16 + (k & 7) * 2;
        *(__nv_bfloat16*)(sm + SB_W1H + off) = hb;
        *(__nv_bfloat16*)(sm + SB_W1L + off) =
            __float2bfloat16(v - __bfloat162float(hb));
    }
    for (int i = tid; i < 128 * 128; i += 256) {
        int n = i >> 7, k = i & 127;
        uint32_t off = (uint32_t)(n * 256) + pch(k >> 3, n) * 16 + (k & 7) * 2;
        float v = ew2[k * 128 + n];
        __nv_bfloat16 hb = __float2bfloat16(v);
        *(__nv_bfloat16*)(sm + SB_W2H + off) = hb;
        *(__nv_bfloat16*)(sm + SB_W2L + off) =
            __float2bfloat16(v - __bfloat162float(hb));
        *(__nv_bfloat16*)(sm + SB_W3H + off) = __float2bfloat16(xw1[k * 128 + n]);
    }
    if (tid < 128) {
        eb2s[tid] = eb2[tid]; xb1s[tid] = xb1[tid];
        infws[tid] = infw[tid]; xw2s[tid] = xw2[tid];
    }
    __syncthreads();

    float eb2r[4], infwr[4], xb1r[4], xw2r[4];
#pragma unroll
    for (int j = 0; j < 4; j++) {
        eb2r[j] = eb2s[cg * 4 + j]; infwr[j] = infws[cg * 4 + j];
        xb1r[j] = xb1s[cg * 4 + j]; xw2r[j] = xw2s[cg * 4 + j];
    }
    const float infbv = infb[0];
    const float xb2v  = xb2[0];
    const float step  = 100.0f / 19.0f;
    const float coeff = -0.5f / (step * step);

    for (int tile = blockIdx.x; tile < NTILES_E; tile += gridDim.x) {
        __syncthreads();            /* s0: prev tile fully consumed */
        int e0 = tile * ETILE;

        if (tid < 64) {
            int e = e0 + tid;
            int d = eidx[e], s = eidx[EE + e];
            dsts[tid] = d; srcs[tid] = s;
            float rx = x[d * 3 + 0] - x[s * 3 + 0];
            float ry = x[d * 3 + 1] - x[s * 3 + 1];
            float rz = x[d * 3 + 2] - x[s * 3 + 2];
            relxs[tid * 3 + 0] = rx; relxs[tid * 3 + 1] = ry; relxs[tid * 3 + 2] = rz;
            xl2s[tid] = sqrtf(rx * rx + ry * ry + rz * rz);
        }
        /* attr part of feat (w=0..13 -> cols 0..27) */
        for (int i = tid; i < 64 * 14; i += 256) {
            int e = i / 14, w = i - 14 * e;
            float2 t = *(const float2*)&eattr[(size_t)(e0 + e) * 28 + 2 * w];
            uint32_t hw, lw; split2(t.x, t.y, hw, lw);
            uint32_t off = (uint32_t)(e * 128) + pch(w >> 2, e) * 16 + (w & 3) * 4;
            *(uint32_t*)(sm + SB_FEATH + off) = hw;
            *(uint32_t*)(sm + SB_FEATL + off) = lw;
        }
        __syncthreads();            /* s1: xl2 ready */

        /* rbf part (w=14..23 -> cols 28..47) */
        for (int i = tid; i < 64 * 10; i += 256) {
            int e = i / 10, w = 14 + (i - 10 * e);
            int k0 = 2 * w - 28;
            float l2v = xl2s[e];
            float d0 = l2v - (float)k0 * step, d1 = l2v - (float)(k0 + 1) * step;
            uint32_t hw, lw;
            split2(expf(coeff * d0 * d0), expf(coeff * d1 * d1), hw, lw);
            uint32_t off = (uint32_t)(e * 128) + pch(w >> 2, e) * 16 + (w & 3) * 4;
            *(uint32_t*)(sm + SB_FEATH + off) = hw;
            *(uint32_t*)(sm + SB_FEATL + off) = lw;
        }
        int dr[8], sr[8];
#pragma unroll
        for (int i = 0; i < 8; i++) { dr[i] = dsts[rg * 8 + i]; sr[i] = srcs[rg * 8 + i]; }
        __syncthreads();            /* s2: feat complete */

        /* ---- GEMM1 (K=48, bf16x3): D = feat @ W1 ---- */
        float acc[8][4];
#pragma unroll
        for (int j = 0; j < 8; j++)
#pragma unroll
            for (int q = 0; q < 4; q++) acc[j][q] = 0.f;
        mma_gemm<3, true, 128, 128>(sm + SB_FEATH, sm + SB_FEATL,
                                    sm + SB_W1H, sm + SB_W1L, acc, wm, wn, lane);
        stage_D(sm + SB_DS, acc, wm, wn, lane);
        __syncthreads();            /* s3: D1 staged */

        /* ---- ep1: t1 = relu(D + g1[dst] + g2[src]) -> bufT hi/lo ---- */
#pragma unroll
        for (int i = 0; i < 8; i++) {
            int e = rg * 8 + i;
            float4 dv = *(const float4*)(sm + SB_DS + e * 512 + pch(cg, e) * 16);
            float4 a = *(const float4*)&g_g1[(size_t)dr[i] * 128 + cg * 4];
            float4 b = *(const float4*)&g_g2[(size_t)sr[i] * 128 + cg * 4];
            float v0 = fmaxf(dv.x + a.x + b.x, 0.f);
            float v1 = fmaxf(dv.y + a.y + b.y, 0.f);
            float v2 = fmaxf(dv.z + a.z + b.z, 0.f);
            float v3 = fmaxf(dv.w + a.w + b.w, 0.f);
            uint32_t h0, l0, h1, l1;
            split2(v0, v1, h0, l0); split2(v2, v3, h1, l1);
            uint32_t off = (uint32_t)(e * 256) + pch(cg >> 1, e) * 16 + (cg & 1) * 8;
            *(uint2*)(sm + SB_TH + off) = make_uint2(h0, h1);
            *(uint2*)(sm + SB_TL + off) = make_uint2(l0, l1);
        }
        __syncthreads();            /* s4: t1 ready */

        /* ---- GEMM2 (K=128, bf16x3): D = t1 @ W2 ---- */
#pragma unroll
        for (int j = 0; j < 8; j++)
#pragma unroll
            for (int q = 0; q < 4; q++) acc[j][q] = 0.f;
        mma_gemm<8, true, 256, 256>(sm + SB_TH, sm + SB_TL,
                                    sm + SB_W2H, sm + SB_W2L, acc, wm, wn, lane);
        stage_D(sm + SB_DS, acc, wm, wn, lane);
        __syncthreads();            /* s5: D2 staged */

        /* ---- ep2: mij = relu(D+eb2); gate; scatter mi; bufM ---- */
        float pd[8];
        float mv[8][4];
#pragma unroll
        for (int i = 0; i < 8; i++) {
            int e = rg * 8 + i;
            float4 dv = *(const float4*)(sm + SB_DS + e * 512 + pch(cg, e) * 16);
            float m0 = fmaxf(dv.x + eb2r[0], 0.f);
            float m1 = fmaxf(dv.y + eb2r[1], 0.f);
            float m2 = fmaxf(dv.z + eb2r[2], 0.f);
            float m3 = fmaxf(dv.w + eb2r[3], 0.f);
            mv[i][0] = m0; mv[i][1] = m1; mv[i][2] = m2; mv[i][3] = m3;
            pd[i] = m0 * infwr[0] + m1 * infwr[1] + m2 * infwr[2] + m3 * infwr[3];
            uint32_t w0, w1;
            PACKBF2(w0, m0, m1); PACKBF2(w1, m2, m3);
            uint32_t off = (uint32_t)(e * 256) + pch(cg >> 1, e) * 16 + (cg & 1) * 8;
            *(uint2*)(sm + SB_BUFM + off) = make_uint2(w0, w1);
        }
#pragma unroll
        for (int o = 16; o > 0; o >>= 1)
#pragma unroll
            for (int i = 0; i < 8; i++)
                pd[i] += __shfl_xor_sync(0xffffffffu, pd[i], o);
#pragma unroll
        for (int i = 0; i < 8; i++) {
            float eij = 1.f / (1.f + expf(-(pd[i] + infbv)));
            red4(&g_mi[(size_t)dr[i] * 128 + cg * 4],
                 mv[i][0] * eij, mv[i][1] * eij, mv[i][2] * eij, mv[i][3] * eij);
        }
        __syncthreads();            /* s6: mij ready */

        /* ---- GEMM3 (K=128, bf16 x1): D = mij @ xw1 ---- */
#pragma unroll
        for (int j = 0; j < 8; j++)
#pragma unroll
            for (int q = 0; q < 4; q++) acc[j][q] = 0.f;
        mma_gemm<8, false, 256, 256>(sm + SB_BUFM, 0,
                                     sm + SB_W3H, 0, acc, wm, wn, lane);
        stage_D(sm + SB_DS, acc, wm, wn, lane);
        __syncthreads();            /* s7: D3 staged */

        /* ---- ep3: xg = relu(D+xb1).xw2 + xb2 ; scatter dx ---- */
        float q[8];
#pragma unroll
        for (int i = 0; i < 8; i++) {
            int e = rg * 8 + i;
            float4 dv = *(const float4*)(sm + SB_DS + e * 512 + pch(cg, e) * 16);
            q[i] = fmaxf(dv.x + xb1r[0], 0.f) * xw2r[0]
                 + fmaxf(dv.y + xb1r[1], 0.f) * xw2r[1]
                 + fmaxf(dv.z + xb1r[2], 0.f) * xw2r[2]
                 + fmaxf(dv.w + xb1r[3], 0.f) * xw2r[3];
        }
#pragma unroll
        for (int o = 16; o > 0; o >>= 1)
#pragma unroll
            for (int i = 0; i < 8; i++)
                q[i] += __shfl_xor_sync(0xffffffffu, q[i], o);
        if (cg < 3) {
#pragma unroll
            for (int i = 0; i < 8; i++) {
                float xg = q[i] + xb2v;
                atomicAdd(&g_dx[dr[i] * 3 + cg],
                          relxs[(rg * 8 + i) * 3 + cg] * xg);
            }
        }
    }
}

/* ================= kernel C1: hidden = relu([mi,h]@nw1+nb1) ============== */
__global__ void __launch_bounds__(512, 1)
k_node1(const float* __restrict__ h, const float* __restrict__ nw1,
        const float* __restrict__ nb1) {
    float* sm = (float*)smraw;
    float* W  = sm;
    float* As = W + 32768;
    int tid = threadIdx.x, tr = tid >> 5, tc = tid & 31;

    for (int i = tid; i < 32768; i += 512) W[i] = nw1[i];
    int n0 = blockIdx.x * 64;
    for (int i = tid; i < 64 * 256; i += 512) {
        int r = i >> 8, k = i & 255, n = n0 + r;
        float v = 0.f;
        if (n < NN) v = (k < 128) ? g_mi[n * 128 + k] : h[n * 128 + (k - 128)];
        As[sidx(k, r)] = v;
    }
    __syncthreads();

    float acc[4][4];
#pragma unroll
    for (int e = 0; e < 4; e++)
#pragma unroll
        for (int j = 0; j < 4; j++) acc[e][j] = nb1[4 * tc + j];
    gemm_acc_f2<256>(As, W, acc, tr, tc);
#pragma unroll
    for (int e = 0; e < 4; e++) {
        int n = n0 + tr * 4 + e;
        if (n < NN)
            *(float4*)&g_tmp[n * 128 + 4 * tc] =
                make_float4(fmaxf(acc[e][0], 0.f), fmaxf(acc[e][1], 0.f),
                            fmaxf(acc[e][2], 0.f), fmaxf(acc[e][3], 0.f));
    }
}

/* ================= kernel C2: out = hidden@nw2+nb2 ======================= */
__global__ void __launch_bounds__(512, 1)
k_node2(const float* __restrict__ nw2, const float* __restrict__ nb2,
        float* __restrict__ out) {
    float* sm = (float*)smraw;
    float* W  = sm;
    float* As = W + 16384;
    int tid = threadIdx.x, tr = tid >> 5, tc = tid & 31;

    for (int i = tid; i < 16384; i += 512) W[i] = nw2[i];
    int n0 = blockIdx.x * 64;
    for (int i = tid; i < 64 * 128; i += 512) {
        int r = i >> 7, k = i & 127, n = n0 + r;
        As[sidx(k, r)] = (n < NN) ? g_tmp[n * 128 + k] : 0.f;
    }
    __syncthreads();

    float acc[4][4];
#pragma unroll
    for (int e = 0; e < 4; e++)
#pragma unroll
        for (int j = 0; j < 4; j++) acc[e][j] = nb2[4 * tc + j];
    gemm_acc_f2<128>(As, W, acc, tr, tc);
#pragma unroll
    for (int e = 0; e < 4; e++) {
        int n = n0 + tr * 4 + e;
        if (n < NN)
            *(float4*)&out[n * 128 + 4 * tc] =
                make_float4(acc[e][0], acc[e][1], acc[e][2], acc[e][3]);
    }
}

/* ================= kernel X: x_out = x + dx/E ============================ */
__global__ void k_xupd(const float* __restrict__ x, float* __restrict__ out) {
    int i = blockIdx.x * blockDim.x + threadIdx.x;
    if (i < NN * 3)
        out[NN * 128 + i] = x[i] + g_dx[i] * (1.0f / (float)EE);
}

/* ========================================================================= */
extern "C" void kernel_launch(void* const* d_in, const int* in_sizes, int n_in,
                              void* d_out, int out_size) {
    const float* h    = (const float*)d_in[0];
    const float* x    = (const float*)d_in[1];
    const float* ea   = (const float*)d_in[2];
    const float* ew1  = (const float*)d_in[3];
    const float* eb1  = (const float*)d_in[4];
    const float* ew2  = (const float*)d_in[5];
    const float* eb2  = (const float*)d_in[6];
    const float* infw = (const float*)d_in[7];
    const float* infb = (const float*)d_in[8];
    const float* nw1  = (const float*)d_in[9];
    const float* nb1  = (const float*)d_in[10];
    const float* nw2  = (const float*)d_in[11];
    const float* nb2  = (const float*)d_in[12];
    const float* xw1  = (const float*)d_in[13];
    const float* xb1  = (const float*)d_in[14];
    const float* xw2  = (const float*)d_in[15];
    const float* xb2  = (const float*)d_in[16];
    const int*   ei   = (const int*)d_in[17];
    float* out = (float*)d_out;

    const size_t smA  = (16384 + 16384 + 8192) * sizeof(float);   /* 163840 */
    const size_t smB  = SB_TOTAL;                                 /* 217088 */
    const size_t smC1 = (32768 + 16384) * sizeof(float);          /* 196608 */
    const size_t smC2 = (16384 + 8192) * sizeof(float);           /*  98304 */

    cudaFuncSetAttribute(k_node_pre, cudaFuncAttributeMaxDynamicSharedMemorySize, (int)smA);
    cudaFuncSetAttribute(k_edge,     cudaFuncAttributeMaxDynamicSharedMemorySize, (int)smB);
    cudaFuncSetAttribute(k_node1,    cudaFuncAttributeMaxDynamicSharedMemorySize, (int)smC1);
    cudaFuncSetAttribute(k_node2,    cudaFuncAttributeMaxDynamicSharedMemorySize, (int)smC2);

    k_node_pre<<<NTILES_N, 512, smA>>>(h, ew1, eb1);
    k_edge<<<148, 256, smB>>>(x, ea, ew1, ew2, eb2, infw, infb,
                              xw1, xb1, xw2, xb2, ei);
    k_node1<<<NTILES_N, 512, smC1>>>(h, nw1, nb1);
    k_node2<<<NTILES_N, 512, smC2>>>(nw2, nb2, out);
    k_xupd<<<(NN * 3 + 255) / 256, 256>>>(x, out);
}